// round 11
// baseline (speedup 1.0000x reference)
#include <cuda_runtime.h>
#include <cuda_bf16.h>

// Problem shape (fixed by reference)
#define VOCAB   1000000
#define EMB     64
#define BATCH   4096
#define SLOTS   26
#define MAX_NNZ 10

static constexpr int PAIRS = BATCH * SLOTS;          // 106,496 (b,s) pairs
static constexpr int LANES_PER_PAIR = 16;            // 16 threads x float4 = 64 floats
static constexpr int THREADS = 256;

// One (batch,slot) pair per 16-thread group; each lane owns one float4 of the
// 64-dim vector, so a row gather is a fully coalesced 256B read (one LDG.E.128
// warp instruction covers 512B = two pairs' rows).
//
// R9 change vs R7 (31.5us, DRAM busy 64%, regs stuck at 32):
//  - __launch_bounds__(256, 2): raise the ptxas register ceiling so the full
//    10-deep gather batch stays register-resident. At 32 regs only ~3 float4
//    loads fit in flight; lat/MLP_eff was the binding term. Trading occupancy
//    (~50-66%) for ~3x per-warp MLP raises total outstanding loads ~1.7x.
//  - single v[10] batch: all ten predicated LDG.128s issued before any FADD
//    consumes a result.
// Kept from R7: int2 key/mask loads (half the LSU issue), __stcs output
// (protect the ~121MB table resident set in the 126MB L2).
__global__ __launch_bounds__(THREADS, 2)
void emb_lookup_kernel(const int* __restrict__ keys,
                       const int* __restrict__ mask,
                       const float* __restrict__ table,
                       float* __restrict__ out)
{
    const int gid  = blockIdx.x * THREADS + threadIdx.x;
    const int pair = gid >> 4;          // (b*SLOTS + s)
    const int lane = gid & 15;          // which float4 of the 64-dim vector
    if (pair >= PAIRS) return;

    const int base = pair * MAX_NNZ;

    // Vectorized key/mask preload: 5x int2 each (40B per pair, 8B aligned).
    const int2* kp = reinterpret_cast<const int2*>(keys + base);
    const int2* mp = reinterpret_cast<const int2*>(mask + base);
    int  k[MAX_NNZ];
    bool m[MAX_NNZ];
#pragma unroll
    for (int j = 0; j < 5; j++) {
        const int2 kk = kp[j];
        const int2 mm = mp[j];
        k[2*j]   = kk.x;  k[2*j+1] = kk.y;
        m[2*j]   = (mm.x != 0);          // works for int32 0/1 AND f32 0.0/1.0 bits
        m[2*j+1] = (mm.y != 0);
    }

    int cnt = 0;
#pragma unroll
    for (int n = 0; n < MAX_NNZ; n++) cnt += m[n] ? 1 : 0;

    // Full-depth batch: 10 independent predicated gathers in flight before the
    // reduction touches any of them (zero-init + @P LDG.E.128).
    float4 v[MAX_NNZ];
#pragma unroll
    for (int n = 0; n < MAX_NNZ; n++) {
        v[n] = make_float4(0.f, 0.f, 0.f, 0.f);
        if (m[n]) {
            v[n] = *reinterpret_cast<const float4*>(
                table + (size_t)k[n] * EMB + lane * 4);
        }
    }

    // Tree-ish reduction with two accumulator chains.
    float4 a0 = make_float4(0.f, 0.f, 0.f, 0.f);
    float4 a1 = make_float4(0.f, 0.f, 0.f, 0.f);
#pragma unroll
    for (int n = 0; n < MAX_NNZ; n += 2) {
        a0.x += v[n].x;   a0.y += v[n].y;   a0.z += v[n].z;   a0.w += v[n].w;
        a1.x += v[n+1].x; a1.y += v[n+1].y; a1.z += v[n+1].z; a1.w += v[n+1].w;
    }

    const float inv = 1.0f / (float)(cnt > 0 ? cnt : 1);
    float4 r;
    r.x = (a0.x + a1.x) * inv;
    r.y = (a0.y + a1.y) * inv;
    r.z = (a0.z + a1.z) * inv;
    r.w = (a0.w + a1.w) * inv;

    // Streaming store: evict-first in L2, protect the table's resident set.
    __stcs(reinterpret_cast<float4*>(out + (size_t)pair * EMB + lane * 4), r);
}

extern "C" void kernel_launch(void* const* d_in, const int* in_sizes, int n_in,
                              void* d_out, int out_size)
{
    const int*   keys  = (const int*)d_in[0];
    const int*   mask  = (const int*)d_in[1];
    const float* table = (const float*)d_in[2];
    float*       out   = (float*)d_out;

    const int total_threads = PAIRS * LANES_PER_PAIR;
    const int blocks = (total_threads + THREADS - 1) / THREADS;
    emb_lookup_kernel<<<blocks, THREADS>>>(keys, mask, table, out);
}